// round 1
// baseline (speedup 1.0000x reference)
#include <cuda_runtime.h>
#include <cuda_bf16.h>
#include <math.h>

// FusedExpertsWrapper: MoE expert FFN
//   gate_up = dispatched[a,b,e,m,:] @ w1[e]  (+ w1_bias[e])     [4096x2048]x[2048x4096] per expert
//   act     = silu(gate_up[..., 0::2]) * gate_up[..., 1::2]
//   out     = act @ w2[e] (+ w2_bias[e])                         [4096x2048]x[2048x2048] per expert
// Output layout: out[e][b*512+m][h], fp32.
//
// Constants (from reference): E=8, H=2048, I=2048, A=1, B=8, M=512 -> 4096 rows/expert.

#define E_EXPERTS 8
#define HDIM      2048
#define IDIM      2048
#define F2I       4096      // 2*I
#define ROWS      4096      // A*B*M rows per expert
#define MSEG      512       // M

// Scratch for activated intermediate: [E][ROWS][IDIM] fp32 = 256 MB
__device__ float g_act[(size_t)E_EXPERTS * ROWS * IDIM];

// ---------------- Tiled SGEMM parameters ----------------
#define BM 128
#define BN 128
#define BK 16
#define TM 8
#define TN 8
// 256 threads: 16x16 thread grid of 8x8 microtiles

// ============================================================
// Kernel 1: gate_up GEMM + bias + SiLU*up epilogue
//   A: dispatched rows (strided by b across expert dim), K=HDIM
//   B: w1[e]  [HDIM x F2I] row-major
//   C: g_act[e][row][i], i = ntile*64 + pair
// ============================================================
__global__ void __launch_bounds__(256, 2)
gemm1_silu(const float* __restrict__ disp,
           const float* __restrict__ w1,
           const float* __restrict__ b1)
{
    const int e     = blockIdx.z;
    const int mtile = blockIdx.y;   // 0..31
    const int ntile = blockIdx.x;   // 0..31 (f-tiles of 128)

    __shared__ float As[BK][BM];
    __shared__ float Bs[BK][BN];

    const int tid = threadIdx.x;

    // --- A tile load mapping: 2 x float4 per thread ---
    const int a_row0 = tid >> 2;          // 0..63
    const int a_k4   = (tid & 3) * 4;     // 0,4,8,12
    const float* Arow0;
    const float* Arow1;
    {
        int r0 = mtile * BM + a_row0;
        int r1 = r0 + 64;
        int b0 = r0 >> 9, m0 = r0 & 511;
        int b1i = r1 >> 9, m1 = r1 & 511;
        Arow0 = disp + (((size_t)(b0 * E_EXPERTS + e)) * MSEG + m0) * (size_t)HDIM;
        Arow1 = disp + (((size_t)(b1i * E_EXPERTS + e)) * MSEG + m1) * (size_t)HDIM;
    }

    // --- B tile load mapping: 2 x float4 per thread ---
    const int b_row0 = tid >> 5;          // 0..7
    const int b_c4   = (tid & 31) * 4;    // 0..124
    const float* Bbase = w1 + (size_t)e * HDIM * F2I + (size_t)ntile * BN;

    float acc[TM][TN];
    #pragma unroll
    for (int i = 0; i < TM; i++)
        #pragma unroll
        for (int j = 0; j < TN; j++) acc[i][j] = 0.0f;

    const int tx = tid & 15;
    const int ty = tid >> 4;
    const int trow = ty * TM;
    const int tcol = tx * TN;

    for (int k0 = 0; k0 < HDIM; k0 += BK) {
        // load A tile (transposed into As[k][row])
        {
            float4 v0 = *reinterpret_cast<const float4*>(Arow0 + k0 + a_k4);
            float4 v1 = *reinterpret_cast<const float4*>(Arow1 + k0 + a_k4);
            As[a_k4 + 0][a_row0]      = v0.x;
            As[a_k4 + 1][a_row0]      = v0.y;
            As[a_k4 + 2][a_row0]      = v0.z;
            As[a_k4 + 3][a_row0]      = v0.w;
            As[a_k4 + 0][a_row0 + 64] = v1.x;
            As[a_k4 + 1][a_row0 + 64] = v1.y;
            As[a_k4 + 2][a_row0 + 64] = v1.z;
            As[a_k4 + 3][a_row0 + 64] = v1.w;
        }
        // load B tile
        #pragma unroll
        for (int i = 0; i < 2; i++) {
            int kk = b_row0 + i * 8;
            float4 v = *reinterpret_cast<const float4*>(Bbase + (size_t)(k0 + kk) * F2I + b_c4);
            *reinterpret_cast<float4*>(&Bs[kk][b_c4]) = v;
        }
        __syncthreads();

        #pragma unroll
        for (int k = 0; k < BK; k++) {
            float4 a0 = *reinterpret_cast<const float4*>(&As[k][trow]);
            float4 a1 = *reinterpret_cast<const float4*>(&As[k][trow + 4]);
            float4 bb0 = *reinterpret_cast<const float4*>(&Bs[k][tcol]);
            float4 bb1 = *reinterpret_cast<const float4*>(&Bs[k][tcol + 4]);
            float ra[TM] = {a0.x, a0.y, a0.z, a0.w, a1.x, a1.y, a1.z, a1.w};
            float rb[TN] = {bb0.x, bb0.y, bb0.z, bb0.w, bb1.x, bb1.y, bb1.z, bb1.w};
            #pragma unroll
            for (int i = 0; i < TM; i++)
                #pragma unroll
                for (int j = 0; j < TN; j++)
                    acc[i][j] = fmaf(ra[i], rb[j], acc[i][j]);
        }
        __syncthreads();
    }

    // Epilogue: bias + SiLU(gate) * up.
    // f-columns fcol = ntile*128 + tcol + j. Even j -> gate, odd j -> up.
    const float* bias = b1 + (size_t)e * F2I + (size_t)ntile * BN + tcol;
    float bg[TN];
    #pragma unroll
    for (int j = 0; j < TN; j++) bg[j] = bias[j];

    #pragma unroll
    for (int i = 0; i < TM; i++) {
        int r = mtile * BM + trow + i;
        float* arow = g_act + (((size_t)e * ROWS) + r) * IDIM
                            + (size_t)ntile * 64 + (tcol >> 1);
        #pragma unroll
        for (int p = 0; p < TN / 2; p++) {
            float g = acc[i][2 * p]     + bg[2 * p];
            float u = acc[i][2 * p + 1] + bg[2 * p + 1];
            float s = g / (1.0f + expf(-g));
            arow[p] = s * u;
        }
    }
}

// ============================================================
// Kernel 2: down GEMM + bias
//   A: g_act[e]  [ROWS x IDIM] contiguous
//   B: w2[e]     [IDIM x HDIM] row-major
//   C: out[e][r][h] fp32
// ============================================================
__global__ void __launch_bounds__(256, 2)
gemm2_bias(const float* __restrict__ w2,
           const float* __restrict__ b2,
           float* __restrict__ out)
{
    const int e     = blockIdx.z;
    const int mtile = blockIdx.y;   // 0..31
    const int ntile = blockIdx.x;   // 0..15

    __shared__ float As[BK][BM];
    __shared__ float Bs[BK][BN];

    const int tid = threadIdx.x;

    const int a_row0 = tid >> 2;
    const int a_k4   = (tid & 3) * 4;
    const float* Abase = g_act + ((size_t)e * ROWS + (size_t)mtile * BM) * IDIM;

    const int b_row0 = tid >> 5;
    const int b_c4   = (tid & 31) * 4;
    const float* Bbase = w2 + (size_t)e * IDIM * HDIM + (size_t)ntile * BN;

    float acc[TM][TN];
    #pragma unroll
    for (int i = 0; i < TM; i++)
        #pragma unroll
        for (int j = 0; j < TN; j++) acc[i][j] = 0.0f;

    const int tx = tid & 15;
    const int ty = tid >> 4;
    const int trow = ty * TM;
    const int tcol = tx * TN;

    for (int k0 = 0; k0 < IDIM; k0 += BK) {
        #pragma unroll
        for (int i = 0; i < 2; i++) {
            int rr = a_row0 + i * 64;
            float4 v = *reinterpret_cast<const float4*>(Abase + (size_t)rr * IDIM + k0 + a_k4);
            As[a_k4 + 0][rr] = v.x;
            As[a_k4 + 1][rr] = v.y;
            As[a_k4 + 2][rr] = v.z;
            As[a_k4 + 3][rr] = v.w;
        }
        #pragma unroll
        for (int i = 0; i < 2; i++) {
            int kk = b_row0 + i * 8;
            float4 v = *reinterpret_cast<const float4*>(Bbase + (size_t)(k0 + kk) * HDIM + b_c4);
            *reinterpret_cast<float4*>(&Bs[kk][b_c4]) = v;
        }
        __syncthreads();

        #pragma unroll
        for (int k = 0; k < BK; k++) {
            float4 a0 = *reinterpret_cast<const float4*>(&As[k][trow]);
            float4 a1 = *reinterpret_cast<const float4*>(&As[k][trow + 4]);
            float4 bb0 = *reinterpret_cast<const float4*>(&Bs[k][tcol]);
            float4 bb1 = *reinterpret_cast<const float4*>(&Bs[k][tcol + 4]);
            float ra[TM] = {a0.x, a0.y, a0.z, a0.w, a1.x, a1.y, a1.z, a1.w};
            float rb[TN] = {bb0.x, bb0.y, bb0.z, bb0.w, bb1.x, bb1.y, bb1.z, bb1.w};
            #pragma unroll
            for (int i = 0; i < TM; i++)
                #pragma unroll
                for (int j = 0; j < TN; j++)
                    acc[i][j] = fmaf(ra[i], rb[j], acc[i][j]);
        }
        __syncthreads();
    }

    const float* bias = b2 + (size_t)e * HDIM + (size_t)ntile * BN + tcol;
    float bb[TN];
    #pragma unroll
    for (int j = 0; j < TN; j++) bb[j] = bias[j];

    #pragma unroll
    for (int i = 0; i < TM; i++) {
        int r = mtile * BM + trow + i;
        float* orow = out + (((size_t)e * ROWS) + r) * (size_t)HDIM
                          + (size_t)ntile * BN + tcol;
        #pragma unroll
        for (int j = 0; j < TN; j++)
            orow[j] = acc[i][j] + bb[j];
    }
}

extern "C" void kernel_launch(void* const* d_in, const int* in_sizes, int n_in,
                              void* d_out, int out_size)
{
    const float* dispatched = (const float*)d_in[0];   // (1,8,8,512,2048)
    const float* w1         = (const float*)d_in[1];   // (8,2048,4096)
    const float* w1_bias    = (const float*)d_in[2];   // (8,4096)
    const float* w2         = (const float*)d_in[3];   // (8,2048,2048)
    const float* w2_bias    = (const float*)d_in[4];   // (8,2048)
    // d_in[5] sparsity_remap (unused by reference), d_in[6]=BD, d_in[7]=S (fixed)
    float* out = (float*)d_out;                        // (8,1,4096,2048)

    (void)in_sizes; (void)n_in; (void)out_size;

    dim3 grid1(F2I / BN, ROWS / BM, E_EXPERTS);   // (32, 32, 8)
    gemm1_silu<<<grid1, 256>>>(dispatched, w1, w1_bias);

    dim3 grid2(HDIM / BN, ROWS / BM, E_EXPERTS);  // (16, 32, 8)
    gemm2_bias<<<grid2, 256>>>(w2, w2_bias, out);
}

// round 3
// speedup vs baseline: 3.1869x; 3.1869x over previous
#include <cuda_runtime.h>
#include <math.h>
#include <stdint.h>

// ============================================================================
// FusedExpertsWrapper — TF32 mma.sync (sm_80+ PTX; runs on tensor pipe).
//   E=8 experts, 4096 rows/expert, H=2048, I=2048, F=2I=4096.
//   GEMM1: gu = x@w1 + b1 ; act = silu(gu_even)*gu_odd
//   GEMM2: out = act@w2 + b2
// Operands pre-rounded to tf32 (RNA). Layouts:
//   A matrices column-major [e][K=2048][M=4096]  (x transposed; act written so)
//   B matrices K-major      [e][K][N]            (w1/w2 native layout, rounded)
// ============================================================================

#define E_EXPERTS 8
#define HDIM      2048
#define IDIM      2048
#define F2I       4096
#define ROWS      4096

__device__ float g_xc [(size_t)E_EXPERTS * HDIM * ROWS];   // x col-major, rounded
__device__ float g_act[(size_t)E_EXPERTS * IDIM * ROWS];   // act col-major, rounded
__device__ float g_w1r[(size_t)E_EXPERTS * HDIM * F2I];    // w1 rounded (native [h][f])
__device__ float g_w2r[(size_t)E_EXPERTS * IDIM * HDIM];   // w2 rounded (native [i][h])

__device__ __forceinline__ float rnd_tf32(float x) {
    float y; asm("cvt.rna.tf32.f32 %0, %1;" : "=f"(y) : "f"(x)); return y;
}

__device__ __forceinline__ uint32_t smem_to_u32(const void* p) {
    uint32_t a;
    asm("{ .reg .u64 t; cvta.to.shared.u64 t, %1; cvt.u32.u64 %0, t; }" : "=r"(a) : "l"(p));
    return a;
}

__device__ __forceinline__ void cp_async16(uint32_t saddr, const void* gaddr) {
    asm volatile("cp.async.cg.shared.global [%0], [%1], 16;" :: "r"(saddr), "l"(gaddr));
}
#define CP_COMMIT() asm volatile("cp.async.commit_group;" ::: "memory")
#define CP_WAIT(N)  asm volatile("cp.async.wait_group %0;" :: "n"(N) : "memory")

#define MMA_TF32(d, a, b) \
    asm volatile("mma.sync.aligned.m16n8k8.row.col.f32.tf32.tf32.f32 " \
        "{%0,%1,%2,%3}, {%4,%5,%6,%7}, {%8,%9}, {%0,%1,%2,%3};" \
        : "+f"((d)[0]), "+f"((d)[1]), "+f"((d)[2]), "+f"((d)[3]) \
        : "r"((a)[0]), "r"((a)[1]), "r"((a)[2]), "r"((a)[3]), \
          "r"((b)[0]), "r"((b)[1]))

// ---------------- GEMM tiling ----------------
#define BM      128
#define BN      128
#define BK      32
#define STAGES  4
#define PAD     8
#define LDS_W   (BM + PAD)                 // 136 floats per k-row (A and B alike)
#define A_FLTS  (BK * LDS_W)               // 4352
#define STG_FLTS (2 * A_FLTS)              // A then B per stage
#define DYN_SMEM (STAGES * STG_FLTS * 4)   // 139264 B

// MODE 0: A=g_xc,  B=g_w1r (N=4096), epilogue: bias+silu*up -> g_act (col-major)
// MODE 1: A=g_act, B=g_w2r (N=2048), epilogue: bias -> out (row-major [e][m][h])
template <int MODE>
__global__ void __launch_bounds__(256, 1)
moe_gemm(const float* __restrict__ Amat,
         const float* __restrict__ Bmat,
         const float* __restrict__ bias,
         float* __restrict__ outp)
{
    extern __shared__ float smem[];
    const int NB = (MODE == 0) ? F2I : HDIM;   // B row width
    const int tid   = threadIdx.x;
    const int mtile = blockIdx.x;              // 0..31
    const int ntile = blockIdx.y;              // 0..(NB/128-1)
    const int e     = blockIdx.z;

    const int wid  = tid >> 5;
    const int lane = tid & 31;
    const int g    = lane >> 2;                // row group 0..7
    const int q    = lane & 3;                 // col-in-group 0..3
    const int warpM = (wid & 3) * 32;          // 4 warps along M
    const int warpN = (wid >> 2) * 64;         // 2 warps along N

    const float* Abase = Amat + (size_t)e * HDIM * ROWS + mtile * BM;      // [k][m], stride 4096
    const float* Bbase = Bmat + (size_t)e * HDIM * NB   + ntile * BN;      // [k][n], stride NB

    const uint32_t smem_u = smem_to_u32(smem);

    float acc[2][8][4];
    #pragma unroll
    for (int mt = 0; mt < 2; mt++)
        #pragma unroll
        for (int nt = 0; nt < 8; nt++)
            #pragma unroll
            for (int r = 0; r < 4; r++) acc[mt][nt][r] = 0.0f;

    // ---- stage loader: 2048 x 16B chunks, 8 per thread ----
    auto load_stage = [&](int s, int c) {
        const uint32_t sbase = smem_u + (uint32_t)s * STG_FLTS * 4;
        const float* Ag = Abase + (size_t)c * BK * ROWS;
        const float* Bg = Bbase + (size_t)c * BK * NB;
        #pragma unroll
        for (int i = 0; i < 4; i++) {
            int idx = tid + i * 256;           // 0..1023
            int row = idx >> 5, col = (idx & 31) << 2;
            cp_async16(sbase + (uint32_t)(row * LDS_W + col) * 4,
                       Ag + (size_t)row * ROWS + col);
        }
        #pragma unroll
        for (int i = 0; i < 4; i++) {
            int idx = tid + i * 256;
            int row = idx >> 5, col = (idx & 31) << 2;
            cp_async16(sbase + (uint32_t)(A_FLTS + row * LDS_W + col) * 4,
                       Bg + (size_t)row * NB + col);
        }
        CP_COMMIT();
    };

    const int NCHUNK = HDIM / BK;   // 64
    #pragma unroll
    for (int c = 0; c < STAGES - 1; c++) load_stage(c, c);

    for (int c = 0; c < NCHUNK; c++) {
        CP_WAIT(STAGES - 2);
        __syncthreads();
        // prefetch into the stage freed by compute(c-1)
        if (c + STAGES - 1 < NCHUNK) load_stage((c + STAGES - 1) & 3, c + STAGES - 1);

        const float* sA = smem + (c & 3) * STG_FLTS;
        const float* sB = sA + A_FLTS;
        // per-thread fragment base pointers (k-row q, element offsets)
        const float* pA = sA + q * LDS_W + warpM + g;
        const float* pB = sB + q * LDS_W + warpN + g;

        #pragma unroll
        for (int ks = 0; ks < 4; ks++) {
            const float* a_ = pA + ks * 8 * LDS_W;
            const float* b_ = pB + ks * 8 * LDS_W;
            uint32_t af[2][4];
            #pragma unroll
            for (int mt = 0; mt < 2; mt++) {
                af[mt][0] = __float_as_uint(a_[mt * 16]);
                af[mt][1] = __float_as_uint(a_[mt * 16 + 8]);
                af[mt][2] = __float_as_uint(a_[4 * LDS_W + mt * 16]);
                af[mt][3] = __float_as_uint(a_[4 * LDS_W + mt * 16 + 8]);
            }
            uint32_t bf[8][2];
            #pragma unroll
            for (int nt = 0; nt < 8; nt++) {
                bf[nt][0] = __float_as_uint(b_[nt * 8]);
                bf[nt][1] = __float_as_uint(b_[4 * LDS_W + nt * 8]);
            }
            #pragma unroll
            for (int mt = 0; mt < 2; mt++)
                #pragma unroll
                for (int nt = 0; nt < 8; nt++)
                    MMA_TF32(acc[mt][nt], af[mt], bf[nt]);
        }
        __syncthreads();
    }

    // ---------------- epilogue ----------------
    // c0:(row g,   col 2q) c1:(g, 2q+1) c2:(g+8, 2q) c3:(g+8, 2q+1)
    if (MODE == 0) {
        const int f0 = ntile * BN + warpN;
        #pragma unroll
        for (int nt = 0; nt < 8; nt++) {
            const int fpair = f0 + nt * 8 + 2 * q;          // gate column (even)
            const float2 bgu = *reinterpret_cast<const float2*>(
                bias + (size_t)e * F2I + fpair);
            const int icol = fpair >> 1;                    // activated column
            float* dcol = g_act + ((size_t)e * IDIM + icol) * ROWS
                                + mtile * BM + warpM;
            #pragma unroll
            for (int mt = 0; mt < 2; mt++) {
                float gg0 = acc[mt][nt][0] + bgu.x;
                float uu0 = acc[mt][nt][1] + bgu.y;
                float gg1 = acc[mt][nt][2] + bgu.x;
                float uu1 = acc[mt][nt][3] + bgu.y;
                float a0 = (gg0 * uu0) / (1.0f + __expf(-gg0));
                float a1 = (gg1 * uu1) / (1.0f + __expf(-gg1));
                dcol[mt * 16 + g]     = rnd_tf32(a0);
                dcol[mt * 16 + g + 8] = rnd_tf32(a1);
            }
        }
    } else {
        const int h0 = ntile * BN + warpN;
        #pragma unroll
        for (int nt = 0; nt < 8; nt++) {
            const int h = h0 + nt * 8 + 2 * q;
            const float2 bb = *reinterpret_cast<const float2*>(
                bias + (size_t)e * HDIM + h);
            #pragma unroll
            for (int mt = 0; mt < 2; mt++) {
                const int m = mtile * BM + warpM + mt * 16 + g;
                float* o0 = outp + ((size_t)e * ROWS + m) * HDIM + h;
                *reinterpret_cast<float2*>(o0) =
                    make_float2(acc[mt][nt][0] + bb.x, acc[mt][nt][1] + bb.y);
                *reinterpret_cast<float2*>(o0 + 8 * (size_t)HDIM) =
                    make_float2(acc[mt][nt][2] + bb.x, acc[mt][nt][3] + bb.y);
            }
        }
    }
}

// ============================ prep kernels ============================

// dispatched [b(8)][e(8)][m(512)][h(2048)] -> g_xc [e][h][r=b*512+m], tf32-rounded
__global__ void prep_transpose_x(const float* __restrict__ in) {
    __shared__ float t[32][33];
    const int e  = blockIdx.z;
    const int r0 = blockIdx.x * 32;    // m-dim (4096)
    const int h0 = blockIdx.y * 32;    // k-dim (2048)
    #pragma unroll
    for (int j = 0; j < 4; j++) {
        int r = r0 + threadIdx.y + j * 8;
        int b = r >> 9, m = r & 511;
        t[threadIdx.y + j * 8][threadIdx.x] =
            in[(((size_t)(b * E_EXPERTS + e) << 9) + m) * HDIM + h0 + threadIdx.x];
    }
    __syncthreads();
    #pragma unroll
    for (int j = 0; j < 4; j++)
        g_xc[((size_t)e * HDIM + h0 + threadIdx.y + j * 8) * ROWS + r0 + threadIdx.x] =
            rnd_tf32(t[threadIdx.x][threadIdx.y + j * 8]);
}

// elementwise tf32-round copy (float4)
__global__ void prep_round(const float4* __restrict__ in, float4* __restrict__ outp) {
    size_t i = (size_t)blockIdx.x * blockDim.x + threadIdx.x;
    float4 v = in[i];
    v.x = rnd_tf32(v.x); v.y = rnd_tf32(v.y); v.z = rnd_tf32(v.z); v.w = rnd_tf32(v.w);
    outp[i] = v;
}

// ============================ host side ============================

extern "C" void kernel_launch(void* const* d_in, const int* in_sizes, int n_in,
                              void* d_out, int out_size)
{
    const float* dispatched = (const float*)d_in[0];   // (1,8,8,512,2048)
    const float* w1         = (const float*)d_in[1];   // (8,2048,4096)
    const float* w1_bias    = (const float*)d_in[2];   // (8,4096)
    const float* w2         = (const float*)d_in[3];   // (8,2048,2048)
    const float* w2_bias    = (const float*)d_in[4];   // (8,2048)
    float* out = (float*)d_out;                        // (8,1,4096,2048) fp32
    (void)in_sizes; (void)n_in; (void)out_size;

    static float *p_act = nullptr, *p_w1r = nullptr, *p_w2r = nullptr;
    static bool init_done = false;
    if (!init_done) {
        cudaGetSymbolAddress((void**)&p_act, g_act);
        cudaGetSymbolAddress((void**)&p_w1r, g_w1r);
        cudaGetSymbolAddress((void**)&p_w2r, g_w2r);
        cudaFuncSetAttribute(moe_gemm<0>, cudaFuncAttributeMaxDynamicSharedMemorySize, DYN_SMEM);
        cudaFuncSetAttribute(moe_gemm<1>, cudaFuncAttributeMaxDynamicSharedMemorySize, DYN_SMEM);
        init_done = true;
    }

    // prep
    prep_transpose_x<<<dim3(ROWS / 32, HDIM / 32, E_EXPERTS), dim3(32, 8)>>>(dispatched);
    prep_round<<<(E_EXPERTS * (size_t)HDIM * F2I / 4) / 256, 256>>>(
        reinterpret_cast<const float4*>(w1), reinterpret_cast<float4*>(p_w1r));
    prep_round<<<(E_EXPERTS * (size_t)IDIM * HDIM / 4) / 256, 256>>>(
        reinterpret_cast<const float4*>(w2), reinterpret_cast<float4*>(p_w2r));

    // GEMM1: x @ w1 -> silu -> g_act
    {
        static float* p_xc = nullptr;
        if (!p_xc) cudaGetSymbolAddress((void**)&p_xc, g_xc);
        moe_gemm<0><<<dim3(ROWS / BM, F2I / BN, E_EXPERTS), 256, DYN_SMEM>>>(
            p_xc, p_w1r, w1_bias, nullptr);
    }
    // GEMM2: act @ w2 -> +bias -> out
    moe_gemm<1><<<dim3(ROWS / BM, HDIM / BN, E_EXPERTS), 256, DYN_SMEM>>>(
        p_act, p_w2r, w2_bias, out);
}